// round 3
// baseline (speedup 1.0000x reference)
#include <cuda_runtime.h>
#include <cuda_bf16.h>
#include <math.h>

// Problem constants (fixed-shape problem)
#define NMAX 50000
#define EMAX 1250000
#define LAT 64
#define HID 128
#define STEPS 5
#define EPSV 1e-6f

// ---------------- scratch (device globals; no allocation allowed) ----------------
__device__ float g_elat[(size_t)EMAX * LAT];     // 320 MB edge latents
__device__ float g_nlatA[(size_t)NMAX * LAT];
__device__ float g_nlatB[(size_t)NMAX * LAT];
__device__ float g_x[(size_t)NMAX * LAT];
__device__ int   g_counts[NMAX];
__device__ int   g_off[NMAX];
__device__ int   g_pos[NMAX];
__device__ int   g_eperm[EMAX];
__device__ int   g_sperm[EMAX];

// ---------------- f32x2 packed-FMA helpers (SASS FFMA2) ----------------
__device__ __forceinline__ unsigned long long pack2(float x) {
    unsigned long long r;
    asm("mov.b64 %0, {%1, %1};" : "=l"(r) : "f"(x));
    return r;
}
__device__ __forceinline__ void ffma2(unsigned long long& acc,
                                      unsigned long long a, unsigned long long b) {
    asm("fma.rn.f32x2 %0, %1, %2, %0;" : "+l"(acc) : "l"(a), "l"(b));
}
__device__ __forceinline__ float2 unpack2(unsigned long long v) {
    float lo, hi;
    asm("mov.b64 {%0, %1}, %2;" : "=f"(lo), "=f"(hi) : "l"(v));
    return make_float2(lo, hi);
}

// ---------------- CSR build ----------------
__global__ void zero_counts_kernel(int* counts, int n) {
    int i = blockIdx.x * blockDim.x + threadIdx.x;
    if (i < n) counts[i] = 0;
}

__global__ void hist_kernel(const int* __restrict__ recv, int* __restrict__ counts, int e) {
    int i = blockIdx.x * blockDim.x + threadIdx.x;
    if (i < e) atomicAdd(&counts[recv[i]], 1);
}

__global__ void scan_kernel(const int* __restrict__ counts, int* __restrict__ off,
                            int* __restrict__ pos, int n) {
    __shared__ int sbuf[1024];
    __shared__ int s_carry;
    int t = threadIdx.x;
    if (t == 0) s_carry = 0;
    __syncthreads();
    for (int base = 0; base < n; base += 1024) {
        int i = base + t;
        int v = (i < n) ? counts[i] : 0;
        sbuf[t] = v;
        __syncthreads();
        for (int d = 1; d < 1024; d <<= 1) {
            int y = 0;
            if (t >= d) y = sbuf[t - d];
            __syncthreads();
            if (t >= d) sbuf[t] += y;
            __syncthreads();
        }
        int incl = sbuf[t];
        int carry = s_carry;
        if (i < n) {
            int excl = carry + incl - v;
            off[i] = excl;
            pos[i] = excl;
        }
        __syncthreads();
        if (t == 1023) s_carry = carry + sbuf[1023];
        __syncthreads();
    }
}

__global__ void scatter_kernel(const int* __restrict__ recv, const int* __restrict__ send,
                               int* __restrict__ pos, int* __restrict__ eperm,
                               int* __restrict__ sperm, int e) {
    int i = blockIdx.x * blockDim.x + threadIdx.x;
    if (i < e) {
        int r = recv[i];
        int p = atomicAdd(&pos[r], 1);
        eperm[p] = i;
        sperm[p] = send[i];
    }
}

// ---------------- GEN aggregation: online softmax, warp-per-node ----------------
__global__ void agg_kernel(const float* __restrict__ nlat, const float* __restrict__ elat,
                           const int* __restrict__ eperm, const int* __restrict__ sperm,
                           const int* __restrict__ off, const int* __restrict__ cnt,
                           float* __restrict__ xout, int n) {
    int warp = (blockIdx.x * blockDim.x + threadIdx.x) >> 5;
    int lane = threadIdx.x & 31;
    if (warp >= n) return;
    int v = warp;
    int start = off[v];
    int c = cnt[v];

    float mx0 = -1e30f, mx1 = -1e30f;
    float s0 = 0.f, s1 = 0.f, t0 = 0.f, t1 = 0.f;

    for (int j = 0; j < c; j++) {
        int eid = eperm[start + j];
        int snd = sperm[start + j];
        const float* er = elat + (size_t)eid * LAT;
        const float* nr = nlat + (size_t)snd * LAT;
        float e0 = er[lane], e1 = er[lane + 32];
        float n0 = nr[lane], n1 = nr[lane + 32];
        float m0 = fmaxf(n0 + e0, 0.f) + EPSV;
        float m1 = fmaxf(n1 + e1, 0.f) + EPSV;
        float nm0 = fmaxf(mx0, m0), nm1 = fmaxf(mx1, m1);
        float c0 = __expf(mx0 - nm0), c1 = __expf(mx1 - nm1);
        float x0 = __expf(m0 - nm0), x1 = __expf(m1 - nm1);
        s0 = s0 * c0 + x0; t0 = t0 * c0 + x0 * m0;
        s1 = s1 * c1 + x1; t1 = t1 * c1 + x1 * m1;
        mx0 = nm0; mx1 = nm1;
    }
    float a0 = (c > 0) ? (t0 / s0) : 0.f;
    float a1 = (c > 0) ? (t1 / s1) : 0.f;
    const float* self = nlat + (size_t)v * LAT;
    float* xo = xout + (size_t)v * LAT;
    xo[lane]      = self[lane]      + a0;
    xo[lane + 32] = self[lane + 32] + a1;
}

// ---------------- packed-FMA tile GEMM (device helper) ----------------
// dst[64][NOUT] = act(src[64][K-ish] @ W[K][NOUT] + b)
// 256 threads. Warp layout: 8 col-groups x 4 row-groups per warp.
// cg = (tid&7) | ((tid>>7)<<3)  in [0,16);  rg = (tid>>3)&15  in [0,16)
// Each thread: 4 rows x G cols (G = NOUT/16, 8 or 4), f32x2 column pairs.
template <int K, int LS, int NOUT, int DS, bool RELU, bool TO_GLOBAL>
__device__ __forceinline__ void gemm_tile(const float* __restrict__ src,
                                          const float* __restrict__ sW,
                                          const float* __restrict__ sB,
                                          float* __restrict__ dst,
                                          int tid, int row0, int M) {
    constexpr int G = NOUT / 16;     // 8 (NOUT=128) or 4 (NOUT=64)
    constexpr int NP = G / 2;        // 4 or 2 pairs
    int cg = (tid & 7) | (((tid >> 7) & 1) << 3);
    int rg = (tid >> 3) & 15;

    unsigned long long acc[4][NP];
    #pragma unroll
    for (int i = 0; i < 4; i++)
        #pragma unroll
        for (int p = 0; p < NP; p++) acc[i][p] = 0ull;

    const float* xbase = src + rg * 4 * LS;
    const float* wbase = sW + cg * G;

    #pragma unroll 4
    for (int k = 0; k < K; k++) {
        unsigned long long w[NP];
        const ulonglong2* wp = reinterpret_cast<const ulonglong2*>(wbase + (size_t)k * NOUT);
        ulonglong2 w01 = wp[0];
        w[0] = w01.x; w[1] = w01.y;
        if (NP == 4) {
            ulonglong2 w23 = wp[1];
            w[2] = w23.x; w[3] = w23.y;
        }
        unsigned long long xs[4];
        #pragma unroll
        for (int i = 0; i < 4; i++) xs[i] = pack2(xbase[i * LS + k]);
        #pragma unroll
        for (int i = 0; i < 4; i++)
            #pragma unroll
            for (int p = 0; p < NP; p++)
                ffma2(acc[i][p], xs[i], w[p]);
    }

    // epilogue
    #pragma unroll
    for (int i = 0; i < 4; i++) {
        int r = rg * 4 + i;
        #pragma unroll
        for (int p = 0; p < NP; p++) {
            float2 v = unpack2(acc[i][p]);
            int c0 = cg * G + 2 * p;
            v.x += sB[c0];
            v.y += sB[c0 + 1];
            if (RELU) { v.x = fmaxf(v.x, 0.f); v.y = fmaxf(v.y, 0.f); }
            if (TO_GLOBAL) {
                int gr = row0 + r;
                if (gr < M)
                    *reinterpret_cast<float2*>(dst + (size_t)gr * NOUT + c0) = v;
            } else {
                dst[r * DS + c0] = v.x;
                dst[r * DS + c0 + 1] = v.y;
            }
        }
    }
}

// ---------------- fused 3-layer MLP (persistent, weights in smem) ----------------
#define HS 130   // padded smem stride for 128-wide activations (4*130 mod 32 == 8)

template <int DIN, int DOUT, bool FINAL_MASK>
__global__ void __launch_bounds__(256, 1)
mlp3_kernel(const float* __restrict__ X,
            const float* __restrict__ W0, const float* __restrict__ b0,
            const float* __restrict__ W1, const float* __restrict__ b1,
            const float* __restrict__ W2, const float* __restrict__ b2,
            float* __restrict__ Y, int M, const float* __restrict__ masksrc) {
    constexpr int XS = (DIN >= 32) ? (DIN + 2) : DIN;   // 66 for DIN=64
    extern __shared__ float sm[];
    float* sW0 = sm;                         // DIN*128
    float* sW1 = sW0 + DIN * HID;            // 128*128
    float* sW2 = sW1 + HID * HID;            // 128*DOUT
    float* sb0 = sW2 + HID * DOUT;           // 128
    float* sb1 = sb0 + HID;                  // 128
    float* sb2 = sb1 + HID;                  // DOUT
    float* sX  = sb2 + DOUT;                 // 64*XS
    float* sH1 = sX + 64 * XS;               // 64*HS
    float* sH2 = sH1 + 64 * HS;              // 64*HS

    int tid = threadIdx.x;
    {
        const float4* w0v = (const float4*)W0;
        float4* s0v = (float4*)sW0;
        for (int i = tid; i < DIN * HID / 4; i += 256) s0v[i] = w0v[i];
        const float4* w1v = (const float4*)W1;
        float4* s1v = (float4*)sW1;
        for (int i = tid; i < HID * HID / 4; i += 256) s1v[i] = w1v[i];
        const float* w2 = W2;
        for (int i = tid; i < HID * DOUT; i += 256) sW2[i] = w2[i];
        if (tid < HID) { sb0[tid] = b0[tid]; sb1[tid] = b1[tid]; }
        if (tid < DOUT) sb2[tid] = b2[tid];
    }
    __syncthreads();

    int ntiles = (M + 63) >> 6;

    for (int tile = blockIdx.x; tile < ntiles; tile += gridDim.x) {
        int row0 = tile << 6;

        // load X tile [64 x DIN] into sX (stride XS)
        for (int i = tid; i < 64 * DIN; i += 256) {
            int r, cc;
            if (DIN == 64) { r = i >> 6; cc = i & 63; }
            else { r = i / DIN; cc = i - r * DIN; }
            int gr = row0 + r;
            sX[r * XS + cc] = (gr < M) ? X[(size_t)gr * DIN + cc] : 0.f;
        }
        __syncthreads();

        // layer 1: [64xDIN] @ [DINx128] -> relu -> sH1
        gemm_tile<DIN, XS, HID, HS, true, false>(sX, sW0, sb0, sH1, tid, row0, M);
        __syncthreads();

        // layer 2: [64x128] @ [128x128] -> relu -> sH2
        gemm_tile<HID, HS, HID, HS, true, false>(sH1, sW1, sb1, sH2, tid, row0, M);
        __syncthreads();

        // layer 3: [64x128] @ [128xDOUT]
        if constexpr (DOUT >= 16) {
            gemm_tile<HID, HS, DOUT, 0, false, true>(sH2, sW2, sb2, Y, tid, row0, M);
        } else {
            // tiny final layer (decoder): 64 rows x DOUT cols, scalar
            if (tid < 64 * DOUT) {
                int r = tid / DOUT;
                int c = tid - r * DOUT;
                float acc = 0.f;
                #pragma unroll 8
                for (int k = 0; k < HID; k++)
                    acc = fmaf(sH2[r * HS + k], sW2[k * DOUT + c], acc);
                int gr = row0 + r;
                if (gr < M) {
                    float v = acc + sb2[c];
                    if (FINAL_MASK) {
                        float a = fabsf(masksrc[(size_t)gr * 2]) +
                                  fabsf(masksrc[(size_t)gr * 2 + 1]);
                        if (a == 0.f) v = 0.f;
                    }
                    Y[(size_t)gr * DOUT + c] = v;
                }
            }
        }
        __syncthreads();
    }
}

// ---------------- host ----------------
static constexpr size_t mlp_smem_bytes(int DIN, int DOUT) {
    int XS = (DIN >= 32) ? (DIN + 2) : DIN;
    return (size_t)(DIN * 128 + 128 * 128 + 128 * DOUT + 128 + 128 + DOUT +
                    64 * XS + 2 * 64 * 130) * sizeof(float);
}

extern "C" void kernel_launch(void* const* d_in, const int* in_sizes, int n_in,
                              void* d_out, int out_size) {
    const float* nodes = (const float*)d_in[0];
    const float* edges = (const float*)d_in[1];
    const int* senders = (const int*)d_in[2];
    const int* receivers = (const int*)d_in[3];
    const float* enW0 = (const float*)d_in[4];
    const float* enb0 = (const float*)d_in[5];
    const float* enW1 = (const float*)d_in[6];
    const float* enb1 = (const float*)d_in[7];
    const float* enW2 = (const float*)d_in[8];
    const float* enb2 = (const float*)d_in[9];
    const float* eeW0 = (const float*)d_in[10];
    const float* eeb0 = (const float*)d_in[11];
    const float* eeW1 = (const float*)d_in[12];
    const float* eeb1 = (const float*)d_in[13];
    const float* eeW2 = (const float*)d_in[14];
    const float* eeb2 = (const float*)d_in[15];
    const float* pW0 = (const float*)d_in[16];
    const float* pb0 = (const float*)d_in[17];
    const float* pW1 = (const float*)d_in[18];
    const float* pb1 = (const float*)d_in[19];
    const float* pW2 = (const float*)d_in[20];
    const float* pb2 = (const float*)d_in[21];
    const float* dW0 = (const float*)d_in[22];
    const float* db0 = (const float*)d_in[23];
    const float* dW1 = (const float*)d_in[24];
    const float* db1 = (const float*)d_in[25];
    const float* dW2 = (const float*)d_in[26];
    const float* db2 = (const float*)d_in[27];
    float* out = (float*)d_out;

    int n = in_sizes[0] / 2;   // 50000
    int e = in_sizes[2];       // 1250000

    // scratch pointers
    float *p_elat, *p_nlatA, *p_nlatB, *p_x;
    int *p_counts, *p_off, *p_pos, *p_eperm, *p_sperm;
    cudaGetSymbolAddress((void**)&p_elat, g_elat);
    cudaGetSymbolAddress((void**)&p_nlatA, g_nlatA);
    cudaGetSymbolAddress((void**)&p_nlatB, g_nlatB);
    cudaGetSymbolAddress((void**)&p_x, g_x);
    cudaGetSymbolAddress((void**)&p_counts, g_counts);
    cudaGetSymbolAddress((void**)&p_off, g_off);
    cudaGetSymbolAddress((void**)&p_pos, g_pos);
    cudaGetSymbolAddress((void**)&p_eperm, g_eperm);
    cudaGetSymbolAddress((void**)&p_sperm, g_sperm);

    // opt-in to large dynamic smem (idempotent, capture-safe host API)
    cudaFuncSetAttribute(mlp3_kernel<2, 64, false>,
                         cudaFuncAttributeMaxDynamicSharedMemorySize,
                         (int)mlp_smem_bytes(2, 64));
    cudaFuncSetAttribute(mlp3_kernel<3, 64, false>,
                         cudaFuncAttributeMaxDynamicSharedMemorySize,
                         (int)mlp_smem_bytes(3, 64));
    cudaFuncSetAttribute(mlp3_kernel<64, 64, false>,
                         cudaFuncAttributeMaxDynamicSharedMemorySize,
                         (int)mlp_smem_bytes(64, 64));
    cudaFuncSetAttribute(mlp3_kernel<64, 2, true>,
                         cudaFuncAttributeMaxDynamicSharedMemorySize,
                         (int)mlp_smem_bytes(64, 2));

    // ---- CSR build (by receiver) ----
    zero_counts_kernel<<<(n + 255) / 256, 256>>>(p_counts, n);
    hist_kernel<<<(e + 255) / 256, 256>>>(receivers, p_counts, e);
    scan_kernel<<<1, 1024>>>(p_counts, p_off, p_pos, n);
    scatter_kernel<<<(e + 255) / 256, 256>>>(receivers, senders, p_pos,
                                             p_eperm, p_sperm, e);

    // ---- encoders ----
    mlp3_kernel<2, 64, false><<<148, 256, mlp_smem_bytes(2, 64)>>>(
        nodes, enW0, enb0, enW1, enb1, enW2, enb2, p_nlatA, n, nullptr);
    mlp3_kernel<3, 64, false><<<148, 256, mlp_smem_bytes(3, 64)>>>(
        edges, eeW0, eeb0, eeW1, eeb1, eeW2, eeb2, p_elat, e, nullptr);

    // ---- processor: 5 GEN message-passing steps ----
    float* cur = p_nlatA;
    float* nxt = p_nlatB;
    int agg_blocks = (n * 32 + 255) / 256;  // one warp per node
    for (int s = 0; s < STEPS; s++) {
        agg_kernel<<<agg_blocks, 256>>>(cur, p_elat, p_eperm, p_sperm,
                                        p_off, p_counts, p_x, n);
        mlp3_kernel<64, 64, false><<<148, 256, mlp_smem_bytes(64, 64)>>>(
            p_x,
            pW0 + (size_t)s * 64 * 128, pb0 + (size_t)s * 128,
            pW1 + (size_t)s * 128 * 128, pb1 + (size_t)s * 128,
            pW2 + (size_t)s * 128 * 64, pb2 + (size_t)s * 64,
            nxt, n, nullptr);
        float* tmp = cur; cur = nxt; nxt = tmp;
    }

    // ---- decoder (+ zero-mask for padded nodes) ----
    mlp3_kernel<64, 2, true><<<148, 256, mlp_smem_bytes(64, 2)>>>(
        cur, dW0, db0, dW1, db1, dW2, db2, out, n, nodes);
}

// round 5
// speedup vs baseline: 1.8372x; 1.8372x over previous
#include <cuda_runtime.h>
#include <cuda_bf16.h>
#include <cstdint>
#include <math.h>

// Problem constants (fixed-shape problem)
#define NMAX 50000
#define EMAX 1250000
#define LAT 64
#define HID 128
#define STEPS 5
#define EPSV 1e-6f

// ---------------- scratch (device globals; no allocation allowed) ----------------
__device__ float g_elat[(size_t)EMAX * LAT];     // 320 MB edge latents
__device__ float g_nlatA[(size_t)NMAX * LAT];
__device__ float g_nlatB[(size_t)NMAX * LAT];
__device__ float g_x[(size_t)NMAX * LAT];
__device__ int   g_counts[NMAX];
__device__ int   g_off[NMAX];
__device__ int   g_pos[NMAX];
__device__ int   g_eperm[EMAX];
__device__ int   g_sperm[EMAX];

// ---------------- bf16 helpers ----------------
// pack (f0 -> lo half, f1 -> hi half) as bf16x2; l = residual pair
__device__ __forceinline__ void split2(float f0, float f1, uint32_t& hp, uint32_t& lp) {
    asm("cvt.rn.bf16x2.f32 %0, %1, %2;" : "=r"(hp) : "f"(f1), "f"(f0));
    float h0 = __uint_as_float(hp << 16);
    float h1 = __uint_as_float(hp & 0xFFFF0000u);
    float r0 = f0 - h0, r1 = f1 - h1;
    asm("cvt.rn.bf16x2.f32 %0, %1, %2;" : "=r"(lp) : "f"(r1), "f"(r0));
}
__device__ __forceinline__ float bf16lo(uint32_t w) { return __uint_as_float(w << 16); }
__device__ __forceinline__ float bf16hi(uint32_t w) { return __uint_as_float(w & 0xFFFF0000u); }

// mma.sync m16n8k16 row.col bf16 -> f32 accumulate
__device__ __forceinline__ void mma16816(float* c, const uint32_t* a, const uint32_t* b) {
    asm volatile(
        "mma.sync.aligned.m16n8k16.row.col.f32.bf16.bf16.f32 "
        "{%0,%1,%2,%3}, {%4,%5,%6,%7}, {%8,%9}, {%0,%1,%2,%3};"
        : "+f"(c[0]), "+f"(c[1]), "+f"(c[2]), "+f"(c[3])
        : "r"(a[0]), "r"(a[1]), "r"(a[2]), "r"(a[3]), "r"(b[0]), "r"(b[1]));
}

// ---------------- smem layout (byte offsets) ----------------
// stride 68 words (136 halves) for K=128 tensors, 36 words (72 halves) for K=64.
#define OFF_W1H 0
#define OFF_W1L 34816
#define OFF_W2H 69632
#define OFF_W2L 87040
#define OFF_W0H 104448
#define OFF_W0L 122880
#define OFF_XH  141312
#define OFF_XL  150528
#define OFF_H1H 159744
#define OFF_H1L 177152
#define OFF_H2H 194560
#define OFF_H2L 211968
#define OFF_B0  229376
#define OFF_B1  229888
#define OFF_B2  230400
#define SM_TOTAL 230656

// convert W [K x N] fp32 -> hi/lo bf16 transposed Wt[n][k], row stride SW halves
template <int K, int N, int SW>
__device__ __forceinline__ void conv_w(const float* __restrict__ W,
                                       uint16_t* __restrict__ wh,
                                       uint16_t* __restrict__ wl, int tid) {
    for (int idx = tid; idx < K * N; idx += 256) {
        int k = idx / N, n = idx - k * N;
        float w = W[idx];
        __nv_bfloat16 h = __float2bfloat16(w);
        float hf = __bfloat162float(h);
        __nv_bfloat16 l = __float2bfloat16(w - hf);
        int o = n * SW + k;
        wh[o] = *(uint16_t*)&h;
        wl[o] = *(uint16_t*)&l;
    }
}

// one layer of 3-term split MMA: acc[NT][4] += A[64 x K] @ W[K x N-slice]
template <int KT, int NT>
__device__ __forceinline__ void mma_block(
    const uint32_t* __restrict__ sAh, const uint32_t* __restrict__ sAl, int asw,
    const uint32_t* __restrict__ sWh, const uint32_t* __restrict__ sWl, int wsw,
    int r0, int nrow0, int g, int q, float acc[NT][4]) {
    #pragma unroll
    for (int nt = 0; nt < NT; nt++)
        #pragma unroll
        for (int j = 0; j < 4; j++) acc[nt][j] = 0.f;

    #pragma unroll
    for (int kt = 0; kt < KT; kt++) {
        int k0 = kt * 8;
        const uint32_t* ar0 = sAh + (r0 + g) * asw + k0 + q;
        const uint32_t* ar1 = sAh + (r0 + g + 8) * asw + k0 + q;
        uint32_t ah[4] = { ar0[0], ar1[0], ar0[4], ar1[4] };
        const uint32_t* al0 = sAl + (r0 + g) * asw + k0 + q;
        const uint32_t* al1 = sAl + (r0 + g + 8) * asw + k0 + q;
        uint32_t al[4] = { al0[0], al1[0], al0[4], al1[4] };
        #pragma unroll
        for (int nt = 0; nt < NT; nt++) {
            int n = nrow0 + nt * 8 + g;
            uint32_t bh[2] = { sWh[n * wsw + k0 + q], sWh[n * wsw + k0 + 4 + q] };
            uint32_t bl[2] = { sWl[n * wsw + k0 + q], sWl[n * wsw + k0 + 4 + q] };
            mma16816(acc[nt], ah, bh);
            mma16816(acc[nt], al, bh);
            mma16816(acc[nt], ah, bl);
        }
    }
}

// epilogue: bias + relu + hi/lo split -> activation buffers (stride dsw words)
template <int NT>
__device__ __forceinline__ void epi_store_act(
    float acc[NT][4], const float* __restrict__ bias,
    uint32_t* __restrict__ dh, uint32_t* __restrict__ dl, int dsw,
    int r0, int ncol0, int g, int q) {
    #pragma unroll
    for (int nt = 0; nt < NT; nt++) {
        int c0 = ncol0 + nt * 8 + 2 * q;
        float b0v = bias[c0], b1v = bias[c0 + 1];
        int w = c0 >> 1;
        uint32_t h, l;
        float f0 = fmaxf(acc[nt][0] + b0v, 0.f);
        float f1 = fmaxf(acc[nt][1] + b1v, 0.f);
        split2(f0, f1, h, l);
        dh[(r0 + g) * dsw + w] = h;
        dl[(r0 + g) * dsw + w] = l;
        float f2 = fmaxf(acc[nt][2] + b0v, 0.f);
        float f3 = fmaxf(acc[nt][3] + b1v, 0.f);
        split2(f2, f3, h, l);
        dh[(r0 + g + 8) * dsw + w] = h;
        dl[(r0 + g + 8) * dsw + w] = l;
    }
}

// ---------------- fused 3-layer MLP on mma.sync (HMMA) ----------------
template <int DIN, int DOUT, bool FINAL_MASK>
__global__ void __launch_bounds__(256, 1)
mlp3_hmma(const float* __restrict__ X,
          const float* __restrict__ W0, const float* __restrict__ b0,
          const float* __restrict__ W1, const float* __restrict__ b1,
          const float* __restrict__ W2, const float* __restrict__ b2,
          float* __restrict__ Y, int M, const float* __restrict__ masksrc) {
    extern __shared__ char smem[];
    uint32_t* sW1h = (uint32_t*)(smem + OFF_W1H);
    uint32_t* sW1l = (uint32_t*)(smem + OFF_W1L);
    uint32_t* sW2h = (uint32_t*)(smem + OFF_W2H);
    uint32_t* sW2l = (uint32_t*)(smem + OFF_W2L);
    uint32_t* sW0h = (uint32_t*)(smem + OFF_W0H);
    uint32_t* sW0l = (uint32_t*)(smem + OFF_W0L);
    uint32_t* sXh  = (uint32_t*)(smem + OFF_XH);
    uint32_t* sXl  = (uint32_t*)(smem + OFF_XL);
    uint32_t* sH1h = (uint32_t*)(smem + OFF_H1H);
    uint32_t* sH1l = (uint32_t*)(smem + OFF_H1L);
    uint32_t* sH2h = (uint32_t*)(smem + OFF_H2H);
    uint32_t* sH2l = (uint32_t*)(smem + OFF_H2L);
    float* sb0 = (float*)(smem + OFF_B0);
    float* sb1 = (float*)(smem + OFF_B1);
    float* sb2 = (float*)(smem + OFF_B2);
    float* sW0f = (float*)(smem + OFF_W0H);   // overlap: fp32 W0 when DIN small
    float* sW2f = (float*)(smem + OFF_W2H);   // overlap: fp32 W2 when DOUT small

    int tid = threadIdx.x;

    // ---- weights -> smem (hi/lo bf16, transposed) ----
    if constexpr (DIN >= 16)
        conv_w<64, 128, 72>(W0, (uint16_t*)sW0h, (uint16_t*)sW0l, tid);
    else
        for (int i = tid; i < DIN * 128; i += 256) sW0f[i] = W0[i];
    conv_w<128, 128, 136>(W1, (uint16_t*)sW1h, (uint16_t*)sW1l, tid);
    if constexpr (DOUT >= 16)
        conv_w<128, 64, 136>(W2, (uint16_t*)sW2h, (uint16_t*)sW2l, tid);
    else
        for (int i = tid; i < 128 * DOUT; i += 256) sW2f[i] = W2[i];
    if (tid < 128) { sb0[tid] = b0[tid]; sb1[tid] = b1[tid]; }
    if (tid < DOUT) sb2[tid] = b2[tid];
    __syncthreads();

    int lane = tid & 31, wid = tid >> 5;
    int g = lane >> 2, q = lane & 3;
    int strip = wid & 3;       // rows strip*16
    int nh = wid >> 2;         // 0/1 (N-half)
    int r0 = strip * 16;

    int ntiles = (M + 63) >> 6;
    for (int tile = blockIdx.x; tile < ntiles; tile += gridDim.x) {
        int row0 = tile << 6;

        // ---- layer 1 ----
        if constexpr (DIN >= 16) {
            // stage X [64 x 64] fp32 -> sXh/sXl (hi/lo bf16)
            {
                int r = tid >> 2, c16 = (tid & 3) * 16;
                int gr = row0 + r;
                const float2* src = (const float2*)(X + (size_t)gr * 64 + c16);
                #pragma unroll
                for (int jj = 0; jj < 8; jj++) {
                    float2 v = (gr < M) ? src[jj] : make_float2(0.f, 0.f);
                    uint32_t h, l;
                    split2(v.x, v.y, h, l);
                    int w = r * 36 + (c16 >> 1) + jj;
                    sXh[w] = h; sXl[w] = l;
                }
            }
            __syncthreads();
            float acc[8][4];
            mma_block<4, 8>(sXh, sXl, 36, sW0h, sW0l, 36, r0, nh * 64, g, q, acc);
            epi_store_act<8>(acc, sb0, sH1h, sH1l, 68, r0, nh * 64, g, q);
            __syncthreads();
        } else {
            // scalar layer 1 (K = 2 or 3)
            int r = tid >> 2, cbase = (tid & 3) * 32;
            int gr = row0 + r;
            float x0 = 0.f, x1 = 0.f, x2 = 0.f;
            if (gr < M) {
                x0 = X[(size_t)gr * DIN];
                x1 = X[(size_t)gr * DIN + 1];
                if (DIN > 2) x2 = X[(size_t)gr * DIN + 2];
            }
            #pragma unroll
            for (int jj = 0; jj < 16; jj++) {
                int c = cbase + jj * 2;
                float f0 = sb0[c]     + x0 * sW0f[c]       + x1 * sW0f[128 + c];
                float f1 = sb0[c + 1] + x0 * sW0f[c + 1]   + x1 * sW0f[128 + c + 1];
                if (DIN > 2) {
                    f0 += x2 * sW0f[256 + c];
                    f1 += x2 * sW0f[256 + c + 1];
                }
                f0 = fmaxf(f0, 0.f); f1 = fmaxf(f1, 0.f);
                uint32_t h, l;
                split2(f0, f1, h, l);
                sH1h[r * 68 + (c >> 1)] = h;
                sH1l[r * 68 + (c >> 1)] = l;
            }
            __syncthreads();
        }

        // ---- layer 2: [64x128] @ [128x128] -> relu -> H2 ----
        {
            float acc[8][4];
            mma_block<8, 8>(sH1h, sH1l, 68, sW1h, sW1l, 68, r0, nh * 64, g, q, acc);
            epi_store_act<8>(acc, sb1, sH2h, sH2l, 68, r0, nh * 64, g, q);
            __syncthreads();
        }

        // ---- layer 3 ----
        if constexpr (DOUT >= 16) {
            float acc[4][4];
            mma_block<8, 4>(sH2h, sH2l, 68, sW2h, sW2l, 68, r0, nh * 32, g, q, acc);
            #pragma unroll
            for (int nt = 0; nt < 4; nt++) {
                int c0 = nh * 32 + nt * 8 + 2 * q;
                float b0v = sb2[c0], b1v = sb2[c0 + 1];
                int gr0 = row0 + r0 + g;
                if (gr0 < M)
                    *(float2*)(Y + (size_t)gr0 * DOUT + c0) =
                        make_float2(acc[nt][0] + b0v, acc[nt][1] + b1v);
                int gr1 = gr0 + 8;
                if (gr1 < M)
                    *(float2*)(Y + (size_t)gr1 * DOUT + c0) =
                        make_float2(acc[nt][2] + b0v, acc[nt][3] + b1v);
            }
            __syncthreads();
        } else {
            // decoder: scalar layer 3 (DOUT = 2), 4 lanes per row
            int r = tid >> 2, ks = (tid & 3) * 32;
            float y0 = 0.f, y1 = 0.f;
            #pragma unroll
            for (int jj = 0; jj < 16; jj++) {
                int kw = (ks >> 1) + jj;
                uint32_t hw = sH2h[r * 68 + kw], lw = sH2l[r * 68 + kw];
                float xe = bf16lo(hw) + bf16lo(lw);
                float xo = bf16hi(hw) + bf16hi(lw);
                int k = ks + jj * 2;
                y0 = fmaf(xe, sW2f[k * 2],           y0);
                y1 = fmaf(xe, sW2f[k * 2 + 1],       y1);
                y0 = fmaf(xo, sW2f[(k + 1) * 2],     y0);
                y1 = fmaf(xo, sW2f[(k + 1) * 2 + 1], y1);
            }
            y0 += __shfl_xor_sync(0xffffffffu, y0, 1);
            y1 += __shfl_xor_sync(0xffffffffu, y1, 1);
            y0 += __shfl_xor_sync(0xffffffffu, y0, 2);
            y1 += __shfl_xor_sync(0xffffffffu, y1, 2);
            int gr = row0 + r;
            if ((tid & 3) == 0 && gr < M) {
                float v0 = y0 + sb2[0], v1 = y1 + sb2[1];
                if (FINAL_MASK) {
                    float a = fabsf(masksrc[(size_t)gr * 2]) +
                              fabsf(masksrc[(size_t)gr * 2 + 1]);
                    if (a == 0.f) { v0 = 0.f; v1 = 0.f; }
                }
                *(float2*)(Y + (size_t)gr * 2) = make_float2(v0, v1);
            }
            __syncthreads();
        }
    }
}

// ---------------- CSR build ----------------
__global__ void zero_counts_kernel(int* counts, int n) {
    int i = blockIdx.x * blockDim.x + threadIdx.x;
    if (i < n) counts[i] = 0;
}

__global__ void hist_kernel(const int* __restrict__ recv, int* __restrict__ counts, int e) {
    int i = blockIdx.x * blockDim.x + threadIdx.x;
    if (i < e) atomicAdd(&counts[recv[i]], 1);
}

__global__ void scan_kernel(const int* __restrict__ counts, int* __restrict__ off,
                            int* __restrict__ pos, int n) {
    __shared__ int sbuf[1024];
    __shared__ int s_carry;
    int t = threadIdx.x;
    if (t == 0) s_carry = 0;
    __syncthreads();
    for (int base = 0; base < n; base += 1024) {
        int i = base + t;
        int v = (i < n) ? counts[i] : 0;
        sbuf[t] = v;
        __syncthreads();
        for (int d = 1; d < 1024; d <<= 1) {
            int y = 0;
            if (t >= d) y = sbuf[t - d];
            __syncthreads();
            if (t >= d) sbuf[t] += y;
            __syncthreads();
        }
        int incl = sbuf[t];
        int carry = s_carry;
        if (i < n) {
            int excl = carry + incl - v;
            off[i] = excl;
            pos[i] = excl;
        }
        __syncthreads();
        if (t == 1023) s_carry = carry + sbuf[1023];
        __syncthreads();
    }
}

__global__ void scatter_kernel(const int* __restrict__ recv, const int* __restrict__ send,
                               int* __restrict__ pos, int* __restrict__ eperm,
                               int* __restrict__ sperm, int e) {
    int i = blockIdx.x * blockDim.x + threadIdx.x;
    if (i < e) {
        int r = recv[i];
        int p = atomicAdd(&pos[r], 1);
        eperm[p] = i;
        sperm[p] = send[i];
    }
}

// ---------------- GEN aggregation: online softmax, warp-per-node ----------------
__global__ void agg_kernel(const float* __restrict__ nlat, const float* __restrict__ elat,
                           const int* __restrict__ eperm, const int* __restrict__ sperm,
                           const int* __restrict__ off, const int* __restrict__ cnt,
                           float* __restrict__ xout, int n) {
    int warp = (blockIdx.x * blockDim.x + threadIdx.x) >> 5;
    int lane = threadIdx.x & 31;
    if (warp >= n) return;
    int v = warp;
    int start = off[v];
    int c = cnt[v];

    float mx0 = -1e30f, mx1 = -1e30f;
    float s0 = 0.f, s1 = 0.f, t0 = 0.f, t1 = 0.f;

    for (int j = 0; j < c; j++) {
        int eid = eperm[start + j];
        int snd = sperm[start + j];
        const float* er = elat + (size_t)eid * LAT;
        const float* nr = nlat + (size_t)snd * LAT;
        float e0 = er[lane], e1 = er[lane + 32];
        float n0 = nr[lane], n1 = nr[lane + 32];
        float m0 = fmaxf(n0 + e0, 0.f) + EPSV;
        float m1 = fmaxf(n1 + e1, 0.f) + EPSV;
        float nm0 = fmaxf(mx0, m0), nm1 = fmaxf(mx1, m1);
        float c0 = __expf(mx0 - nm0), c1 = __expf(mx1 - nm1);
        float x0 = __expf(m0 - nm0), x1 = __expf(m1 - nm1);
        s0 = s0 * c0 + x0; t0 = t0 * c0 + x0 * m0;
        s1 = s1 * c1 + x1; t1 = t1 * c1 + x1 * m1;
        mx0 = nm0; mx1 = nm1;
    }
    float a0 = (c > 0) ? (t0 / s0) : 0.f;
    float a1 = (c > 0) ? (t1 / s1) : 0.f;
    const float* self = nlat + (size_t)v * LAT;
    float* xo = xout + (size_t)v * LAT;
    xo[lane]      = self[lane]      + a0;
    xo[lane + 32] = self[lane + 32] + a1;
}

// ---------------- host ----------------
extern "C" void kernel_launch(void* const* d_in, const int* in_sizes, int n_in,
                              void* d_out, int out_size) {
    const float* nodes = (const float*)d_in[0];
    const float* edges = (const float*)d_in[1];
    const int* senders = (const int*)d_in[2];
    const int* receivers = (const int*)d_in[3];
    const float* enW0 = (const float*)d_in[4];
    const float* enb0 = (const float*)d_in[5];
    const float* enW1 = (const float*)d_in[6];
    const float* enb1 = (const float*)d_in[7];
    const float* enW2 = (const float*)d_in[8];
    const float* enb2 = (const float*)d_in[9];
    const float* eeW0 = (const float*)d_in[10];
    const float* eeb0 = (const float*)d_in[11];
    const float* eeW1 = (const float*)d_in[12];
    const float* eeb1 = (const float*)d_in[13];
    const float* eeW2 = (const float*)d_in[14];
    const float* eeb2 = (const float*)d_in[15];
    const float* pW0 = (const float*)d_in[16];
    const float* pb0 = (const float*)d_in[17];
    const float* pW1 = (const float*)d_in[18];
    const float* pb1 = (const float*)d_in[19];
    const float* pW2 = (const float*)d_in[20];
    const float* pb2 = (const float*)d_in[21];
    const float* dW0 = (const float*)d_in[22];
    const float* db0 = (const float*)d_in[23];
    const float* dW1 = (const float*)d_in[24];
    const float* db1 = (const float*)d_in[25];
    const float* dW2 = (const float*)d_in[26];
    const float* db2 = (const float*)d_in[27];
    float* out = (float*)d_out;

    int n = in_sizes[0] / 2;   // 50000
    int e = in_sizes[2];       // 1250000

    // scratch pointers
    float *p_elat, *p_nlatA, *p_nlatB, *p_x;
    int *p_counts, *p_off, *p_pos, *p_eperm, *p_sperm;
    cudaGetSymbolAddress((void**)&p_elat, g_elat);
    cudaGetSymbolAddress((void**)&p_nlatA, g_nlatA);
    cudaGetSymbolAddress((void**)&p_nlatB, g_nlatB);
    cudaGetSymbolAddress((void**)&p_x, g_x);
    cudaGetSymbolAddress((void**)&p_counts, g_counts);
    cudaGetSymbolAddress((void**)&p_off, g_off);
    cudaGetSymbolAddress((void**)&p_pos, g_pos);
    cudaGetSymbolAddress((void**)&p_eperm, g_eperm);
    cudaGetSymbolAddress((void**)&p_sperm, g_sperm);

    cudaFuncSetAttribute(mlp3_hmma<2, 64, false>,
                         cudaFuncAttributeMaxDynamicSharedMemorySize, SM_TOTAL);
    cudaFuncSetAttribute(mlp3_hmma<3, 64, false>,
                         cudaFuncAttributeMaxDynamicSharedMemorySize, SM_TOTAL);
    cudaFuncSetAttribute(mlp3_hmma<64, 64, false>,
                         cudaFuncAttributeMaxDynamicSharedMemorySize, SM_TOTAL);
    cudaFuncSetAttribute(mlp3_hmma<64, 2, true>,
                         cudaFuncAttributeMaxDynamicSharedMemorySize, SM_TOTAL);

    // ---- CSR build (by receiver) ----
    zero_counts_kernel<<<(n + 255) / 256, 256>>>(p_counts, n);
    hist_kernel<<<(e + 255) / 256, 256>>>(receivers, p_counts, e);
    scan_kernel<<<1, 1024>>>(p_counts, p_off, p_pos, n);
    scatter_kernel<<<(e + 255) / 256, 256>>>(receivers, senders, p_pos,
                                             p_eperm, p_sperm, e);

    // ---- encoders ----
    mlp3_hmma<2, 64, false><<<148, 256, SM_TOTAL>>>(
        nodes, enW0, enb0, enW1, enb1, enW2, enb2, p_nlatA, n, nullptr);
    mlp3_hmma<3, 64, false><<<148, 256, SM_TOTAL>>>(
        edges, eeW0, eeb0, eeW1, eeb1, eeW2, eeb2, p_elat, e, nullptr);

    // ---- processor: 5 GEN message-passing steps ----
    float* cur = p_nlatA;
    float* nxt = p_nlatB;
    int agg_blocks = (n * 32 + 255) / 256;  // one warp per node
    for (int s = 0; s < STEPS; s++) {
        agg_kernel<<<agg_blocks, 256>>>(cur, p_elat, p_eperm, p_sperm,
                                        p_off, p_counts, p_x, n);
        mlp3_hmma<64, 64, false><<<148, 256, SM_TOTAL>>>(
            p_x,
            pW0 + (size_t)s * 64 * 128, pb0 + (size_t)s * 128,
            pW1 + (size_t)s * 128 * 128, pb1 + (size_t)s * 128,
            pW2 + (size_t)s * 128 * 64, pb2 + (size_t)s * 64,
            nxt, n, nullptr);
        float* tmp = cur; cur = nxt; nxt = tmp;
    }

    // ---- decoder (+ zero-mask for padded nodes) ----
    mlp3_hmma<64, 2, true><<<148, 256, SM_TOTAL>>>(
        cur, dW0, db0, dW1, db1, dW2, db2, out, n, nodes);
}